// round 3
// baseline (speedup 1.0000x reference)
#include <cuda_runtime.h>
#include <cstdint>

#define N_NODES 100000
#define N_EDGES 1600000
#define IN_F 64
#define OUT_F 64
#define SUPPORT 3

#define M_BINS (SUPPORT * N_NODES)          // 300000 (support, dest-row) bins
#define TOT_E  (SUPPORT * N_EDGES)          // 4.8M edges
#define SCAN_BS 1024
#define NBLK ((M_BINS + SCAN_BS - 1) / SCAN_BS)   // 293

// ---- static scratch (no runtime allocation) -------------------------------
__device__ float g_Z[(size_t)SUPPORT * N_NODES * OUT_F];   // 76.8 MB: X @ W_k
__device__ int   g_count[M_BINS];
__device__ int   g_start[M_BINS + 1];
__device__ int   g_cursor[M_BINS];
__device__ int   g_partial[SCAN_BS];                       // >= NBLK
__device__ int   g_zidx[TOT_E];                            // k*N + col, bin-sorted
__device__ float g_valss[TOT_E];                           // val, bin-sorted

// ---------------------------------------------------------------------------
// GEMM: Z[k][n][:] = X[n][:] @ W[k*64:(k+1)*64][:]
// ---------------------------------------------------------------------------
__global__ __launch_bounds__(256) void gemm_kernel(const float* __restrict__ X,
                                                   const float* __restrict__ W) {
    __shared__ float  Xs[64][64];
    __shared__ float4 Ws4[64][16];

    const int k     = blockIdx.y;
    const int rbase = blockIdx.x * 64;
    const int tid   = threadIdx.x;

    #pragma unroll
    for (int i = tid; i < 64 * 16; i += 256) {
        int r  = i >> 4;
        int c4 = i & 15;
        int gr = rbase + r;
        float4 v = make_float4(0.f, 0.f, 0.f, 0.f);
        if (gr < N_NODES)
            v = *reinterpret_cast<const float4*>(X + (size_t)gr * IN_F + c4 * 4);
        Xs[r][c4 * 4 + 0] = v.x;
        Xs[r][c4 * 4 + 1] = v.y;
        Xs[r][c4 * 4 + 2] = v.z;
        Xs[r][c4 * 4 + 3] = v.w;
    }
    #pragma unroll
    for (int i = tid; i < 64 * 16; i += 256) {
        int j  = i >> 4;
        int c4 = i & 15;
        Ws4[j][c4] = *reinterpret_cast<const float4*>(W + (size_t)(k * 64 + j) * OUT_F + c4 * 4);
    }
    __syncthreads();

    const int ty = tid >> 4;
    const int tx = tid & 15;

    float acc[4][4];
    #pragma unroll
    for (int i = 0; i < 4; i++)
        #pragma unroll
        for (int c = 0; c < 4; c++) acc[i][c] = 0.f;

    #pragma unroll
    for (int j = 0; j < 64; j++) {
        float4 b = Ws4[j][tx];
        #pragma unroll
        for (int i = 0; i < 4; i++) {
            float a = Xs[ty * 4 + i][j];
            acc[i][0] += a * b.x;
            acc[i][1] += a * b.y;
            acc[i][2] += a * b.z;
            acc[i][3] += a * b.w;
        }
    }

    float* Zk = g_Z + (size_t)k * N_NODES * OUT_F;
    #pragma unroll
    for (int i = 0; i < 4; i++) {
        int gr = rbase + ty * 4 + i;
        if (gr < N_NODES) {
            float4 o = make_float4(acc[i][0], acc[i][1], acc[i][2], acc[i][3]);
            *reinterpret_cast<float4*>(Zk + (size_t)gr * OUT_F + tx * 4) = o;
        }
    }
}

// ---------------------------------------------------------------------------
// Counting-sort pipeline
// ---------------------------------------------------------------------------
__global__ __launch_bounds__(256) void zero_kernel() {
    int i = blockIdx.x * 256 + threadIdx.x;
    if (i < M_BINS) g_count[i] = 0;
}

__global__ __launch_bounds__(256) void hist_kernel(const int* __restrict__ rows) {
    int e = blockIdx.x * 256 + threadIdx.x;
    if (e >= TOT_E) return;
    int k = e / N_EDGES;
    int r = __ldg(rows + e);
    atomicAdd(&g_count[k * N_NODES + r], 1);
}

// Block-local exclusive scan; g_partial[b] = block total.
__global__ __launch_bounds__(SCAN_BS) void scanA_kernel() {
    __shared__ int s[SCAN_BS];
    int t = threadIdx.x;
    int i = blockIdx.x * SCAN_BS + t;
    int v = (i < M_BINS) ? g_count[i] : 0;
    s[t] = v;
    __syncthreads();
    #pragma unroll
    for (int off = 1; off < SCAN_BS; off <<= 1) {
        int x = (t >= off) ? s[t - off] : 0;
        __syncthreads();
        s[t] += x;
        __syncthreads();
    }
    if (i < M_BINS) g_start[i] = s[t] - v;          // exclusive within block
    if (t == SCAN_BS - 1) g_partial[blockIdx.x] = s[t];
}

// Exclusive scan of the block totals (single block).
__global__ __launch_bounds__(512) void scanB_kernel() {
    __shared__ int s[512];
    int t = threadIdx.x;
    int v = (t < NBLK) ? g_partial[t] : 0;
    s[t] = v;
    __syncthreads();
    #pragma unroll
    for (int off = 1; off < 512; off <<= 1) {
        int x = (t >= off) ? s[t - off] : 0;
        __syncthreads();
        s[t] += x;
        __syncthreads();
    }
    if (t < NBLK) g_partial[t] = s[t] - v;
}

// Add block offsets, init cursors, cap the offsets array.
__global__ __launch_bounds__(SCAN_BS) void scanC_kernel() {
    int i = blockIdx.x * SCAN_BS + threadIdx.x;
    if (i < M_BINS) {
        int st = g_start[i] + g_partial[blockIdx.x];
        g_start[i]  = st;
        g_cursor[i] = st;
    }
    if (i == 0) g_start[M_BINS] = TOT_E;
}

// Reorder (k*N+col, val) into bin order.
__global__ __launch_bounds__(256) void scatter_kernel(const int* __restrict__ rows,
                                                      const int* __restrict__ cols,
                                                      const float* __restrict__ vals) {
    int e = blockIdx.x * 256 + threadIdx.x;
    if (e >= TOT_E) return;
    int k = e / N_EDGES;
    int r = __ldg(rows + e);
    int c = __ldg(cols + e);
    float v = __ldg(vals + e);
    int pos = atomicAdd(&g_cursor[k * N_NODES + r], 1);
    g_zidx[pos]  = k * N_NODES + c;
    g_valss[pos] = v;
}

// ---------------------------------------------------------------------------
// Accumulate: one warp per destination node (uniform loop bounds per warp).
// lane owns float2 slot; out[n] = bias + sum over all 3 supports' edges.
// ---------------------------------------------------------------------------
__global__ __launch_bounds__(256) void accum_kernel(const float* __restrict__ bias,
                                                    float* __restrict__ out) {
    int t    = blockIdx.x * 256 + threadIdx.x;
    int n    = t >> 5;
    int lane = t & 31;
    if (n >= N_NODES) return;

    float2 acc = make_float2(0.f, 0.f);

    #pragma unroll
    for (int k = 0; k < SUPPORT; k++) {
        int bin  = k * N_NODES + n;
        int e    = __ldg(&g_start[bin]);
        int eend = __ldg(&g_start[bin + 1]);

        // 2-way unrolled: two independent gathers in flight
        for (; e + 2 <= eend; e += 2) {
            int   z0 = __ldg(g_zidx + e);
            int   z1 = __ldg(g_zidx + e + 1);
            float v0 = __ldg(g_valss + e);
            float v1 = __ldg(g_valss + e + 1);
            float2 f0 = *reinterpret_cast<const float2*>(g_Z + (size_t)z0 * OUT_F + lane * 2);
            float2 f1 = *reinterpret_cast<const float2*>(g_Z + (size_t)z1 * OUT_F + lane * 2);
            acc.x += v0 * f0.x;
            acc.y += v0 * f0.y;
            acc.x += v1 * f1.x;
            acc.y += v1 * f1.y;
        }
        if (e < eend) {
            int   z0 = __ldg(g_zidx + e);
            float v0 = __ldg(g_valss + e);
            float2 f0 = *reinterpret_cast<const float2*>(g_Z + (size_t)z0 * OUT_F + lane * 2);
            acc.x += v0 * f0.x;
            acc.y += v0 * f0.y;
        }
    }

    float2 b2 = *reinterpret_cast<const float2*>(bias + lane * 2);
    float2 o  = make_float2(b2.x + acc.x, b2.y + acc.y);
    *reinterpret_cast<float2*>(out + (size_t)n * OUT_F + lane * 2) = o;
}

// ---------------------------------------------------------------------------
extern "C" void kernel_launch(void* const* d_in, const int* in_sizes, int n_in,
                              void* d_out, int out_size) {
    const float* X     = (const float*)d_in[0];
    const int*   erows = (const int*)  d_in[1];
    const int*   ecols = (const int*)  d_in[2];
    const float* evals = (const float*)d_in[3];
    const float* W     = (const float*)d_in[4];
    const float* bias  = (const float*)d_in[5];
    float*       out   = (float*)d_out;

    // Dense GEMM first (independent of the sort pipeline)
    dim3 ggrid((N_NODES + 63) / 64, SUPPORT);
    gemm_kernel<<<ggrid, 256>>>(X, W);

    // Counting sort of edges by (support, dest row)
    int ebl = (TOT_E + 255) / 256;
    zero_kernel<<<(M_BINS + 255) / 256, 256>>>();
    hist_kernel<<<ebl, 256>>>(erows);
    scanA_kernel<<<NBLK, SCAN_BS>>>();
    scanB_kernel<<<1, 512>>>();
    scanC_kernel<<<NBLK, SCAN_BS>>>();
    scatter_kernel<<<ebl, 256>>>(erows, ecols, evals);

    // Gather-accumulate, one warp per node, no atomics
    int ablocks = (N_NODES * 32 + 255) / 256;
    accum_kernel<<<ablocks, 256>>>(bias, out);
}

// round 4
// speedup vs baseline: 1.0575x; 1.0575x over previous
#include <cuda_runtime.h>
#include <cstdint>

#define N_NODES 100000
#define N_EDGES 1600000
#define IN_F 64
#define OUT_F 64
#define SUPPORT 3

#define TOT_E  (SUPPORT * N_EDGES)                 // 4.8M edges
#define SCAN_BS 1024
#define NBLK ((N_NODES + SCAN_BS - 1) / SCAN_BS)   // 98 blocks

// ---- static scratch (no runtime allocation) -------------------------------
__device__ float              g_Z[(size_t)SUPPORT * N_NODES * OUT_F];  // 76.8 MB
__device__ int                g_count[N_NODES];
__device__ int                g_start[N_NODES + 1];
__device__ int                g_cursor[N_NODES];
__device__ int                g_partial[SCAN_BS];
__device__ unsigned long long g_pairs[TOT_E];      // (val<<32 | zidx), bin-sorted

// ---------------------------------------------------------------------------
// GEMM: Z[k][n][:] = X[n][:] @ W[k*64:(k+1)*64][:]
// X tile kept as float4-along-features; j walked in chunks of 4 so the inner
// loop is 2x LDS.128 per j per thread (was 1 vec + 4 scalar LDS).
// ---------------------------------------------------------------------------
__global__ __launch_bounds__(256) void gemm_kernel(const float* __restrict__ X,
                                                   const float* __restrict__ W) {
    __shared__ float4 Xs4[64][16];    // [row][j/4]
    __shared__ float4 Ws4[64][16];    // [j][col/4]

    const int k     = blockIdx.y;
    const int rbase = blockIdx.x * 64;
    const int tid   = threadIdx.x;

    #pragma unroll
    for (int i = tid; i < 64 * 16; i += 256) {
        int r  = i >> 4;
        int c4 = i & 15;
        int gr = rbase + r;
        float4 v = make_float4(0.f, 0.f, 0.f, 0.f);
        if (gr < N_NODES)
            v = *reinterpret_cast<const float4*>(X + (size_t)gr * IN_F + c4 * 4);
        Xs4[r][c4] = v;
    }
    #pragma unroll
    for (int i = tid; i < 64 * 16; i += 256) {
        int j  = i >> 4;
        int c4 = i & 15;
        Ws4[j][c4] = *reinterpret_cast<const float4*>(W + (size_t)(k * 64 + j) * OUT_F + c4 * 4);
    }
    __syncthreads();

    const int ty = tid >> 4;   // row group (4 rows)
    const int tx = tid & 15;   // col quad

    float acc[4][4];
    #pragma unroll
    for (int i = 0; i < 4; i++)
        #pragma unroll
        for (int c = 0; c < 4; c++) acc[i][c] = 0.f;

    #pragma unroll
    for (int j0 = 0; j0 < 64; j0 += 4) {
        float4 b0 = Ws4[j0 + 0][tx];
        float4 b1 = Ws4[j0 + 1][tx];
        float4 b2 = Ws4[j0 + 2][tx];
        float4 b3 = Ws4[j0 + 3][tx];
        #pragma unroll
        for (int i = 0; i < 4; i++) {
            float4 a = Xs4[ty * 4 + i][j0 >> 2];   // 4 consecutive j values
            acc[i][0] += a.x * b0.x + a.y * b1.x + a.z * b2.x + a.w * b3.x;
            acc[i][1] += a.x * b0.y + a.y * b1.y + a.z * b2.y + a.w * b3.y;
            acc[i][2] += a.x * b0.z + a.y * b1.z + a.z * b2.z + a.w * b3.z;
            acc[i][3] += a.x * b0.w + a.y * b1.w + a.z * b2.w + a.w * b3.w;
        }
    }

    float* Zk = g_Z + (size_t)k * N_NODES * OUT_F;
    #pragma unroll
    for (int i = 0; i < 4; i++) {
        int gr = rbase + ty * 4 + i;
        if (gr < N_NODES) {
            float4 o = make_float4(acc[i][0], acc[i][1], acc[i][2], acc[i][3]);
            *reinterpret_cast<float4*>(Zk + (size_t)gr * OUT_F + tx * 4) = o;
        }
    }
}

// ---------------------------------------------------------------------------
// Counting sort by destination row (single bin space, all supports merged)
// ---------------------------------------------------------------------------
__global__ __launch_bounds__(256) void zero_kernel() {
    int i = blockIdx.x * 256 + threadIdx.x;
    if (i < N_NODES) g_count[i] = 0;
}

__global__ __launch_bounds__(256) void hist_kernel(const int* __restrict__ rows) {
    int e = blockIdx.x * 256 + threadIdx.x;
    if (e >= TOT_E) return;
    atomicAdd(&g_count[__ldg(rows + e)], 1);
}

__global__ __launch_bounds__(SCAN_BS) void scanA_kernel() {
    __shared__ int s[SCAN_BS];
    int t = threadIdx.x;
    int i = blockIdx.x * SCAN_BS + t;
    int v = (i < N_NODES) ? g_count[i] : 0;
    s[t] = v;
    __syncthreads();
    #pragma unroll
    for (int off = 1; off < SCAN_BS; off <<= 1) {
        int x = (t >= off) ? s[t - off] : 0;
        __syncthreads();
        s[t] += x;
        __syncthreads();
    }
    if (i < N_NODES) g_start[i] = s[t] - v;
    if (t == SCAN_BS - 1) g_partial[blockIdx.x] = s[t];
}

__global__ __launch_bounds__(128) void scanB_kernel() {
    __shared__ int s[128];
    int t = threadIdx.x;
    int v = (t < NBLK) ? g_partial[t] : 0;
    s[t] = v;
    __syncthreads();
    #pragma unroll
    for (int off = 1; off < 128; off <<= 1) {
        int x = (t >= off) ? s[t - off] : 0;
        __syncthreads();
        s[t] += x;
        __syncthreads();
    }
    if (t < NBLK) g_partial[t] = s[t] - v;
}

__global__ __launch_bounds__(SCAN_BS) void scanC_kernel() {
    int i = blockIdx.x * SCAN_BS + threadIdx.x;
    if (i < N_NODES) {
        int st = g_start[i] + g_partial[blockIdx.x];
        g_start[i]  = st;
        g_cursor[i] = st;
    }
    if (i == 0) g_start[N_NODES] = TOT_E;
}

// Reorder (zidx = k*N+col, val) into bin order as packed 8B payloads.
__global__ __launch_bounds__(256) void scatter_kernel(const int* __restrict__ rows,
                                                      const int* __restrict__ cols,
                                                      const float* __restrict__ vals) {
    int e = blockIdx.x * 256 + threadIdx.x;
    if (e >= TOT_E) return;
    int   k = e / N_EDGES;
    int   r = __ldg(rows + e);
    int   c = __ldg(cols + e);
    float v = __ldg(vals + e);
    int pos = atomicAdd(&g_cursor[r], 1);
    unsigned long long pk =
        ((unsigned long long)__float_as_uint(v) << 32) |
        (unsigned int)(k * N_NODES + c);
    g_pairs[pos] = pk;
}

// ---------------------------------------------------------------------------
// Accumulate: one warp per destination node, single loop over all supports'
// edges (avg 48), 4-way unrolled gathers (MLP=4), no atomics.
// ---------------------------------------------------------------------------
__global__ __launch_bounds__(256) void accum_kernel(const float* __restrict__ bias,
                                                    float* __restrict__ out) {
    int t    = blockIdx.x * 256 + threadIdx.x;
    int n    = t >> 5;
    int lane = t & 31;
    if (n >= N_NODES) return;

    int e    = __ldg(&g_start[n]);
    int eend = __ldg(&g_start[n + 1]);

    float2 acc = make_float2(0.f, 0.f);

    for (; e + 4 <= eend; e += 4) {
        unsigned long long p0 = __ldg(g_pairs + e + 0);
        unsigned long long p1 = __ldg(g_pairs + e + 1);
        unsigned long long p2 = __ldg(g_pairs + e + 2);
        unsigned long long p3 = __ldg(g_pairs + e + 3);
        int z0 = (int)(unsigned int)p0;
        int z1 = (int)(unsigned int)p1;
        int z2 = (int)(unsigned int)p2;
        int z3 = (int)(unsigned int)p3;
        float v0 = __uint_as_float((unsigned int)(p0 >> 32));
        float v1 = __uint_as_float((unsigned int)(p1 >> 32));
        float v2 = __uint_as_float((unsigned int)(p2 >> 32));
        float v3 = __uint_as_float((unsigned int)(p3 >> 32));
        float2 f0 = *reinterpret_cast<const float2*>(g_Z + (size_t)z0 * OUT_F + lane * 2);
        float2 f1 = *reinterpret_cast<const float2*>(g_Z + (size_t)z1 * OUT_F + lane * 2);
        float2 f2 = *reinterpret_cast<const float2*>(g_Z + (size_t)z2 * OUT_F + lane * 2);
        float2 f3 = *reinterpret_cast<const float2*>(g_Z + (size_t)z3 * OUT_F + lane * 2);
        acc.x += v0 * f0.x; acc.y += v0 * f0.y;
        acc.x += v1 * f1.x; acc.y += v1 * f1.y;
        acc.x += v2 * f2.x; acc.y += v2 * f2.y;
        acc.x += v3 * f3.x; acc.y += v3 * f3.y;
    }
    for (; e < eend; e++) {
        unsigned long long p0 = __ldg(g_pairs + e);
        int   z0 = (int)(unsigned int)p0;
        float v0 = __uint_as_float((unsigned int)(p0 >> 32));
        float2 f0 = *reinterpret_cast<const float2*>(g_Z + (size_t)z0 * OUT_F + lane * 2);
        acc.x += v0 * f0.x; acc.y += v0 * f0.y;
    }

    float2 b2 = *reinterpret_cast<const float2*>(bias + lane * 2);
    float2 o  = make_float2(b2.x + acc.x, b2.y + acc.y);
    *reinterpret_cast<float2*>(out + (size_t)n * OUT_F + lane * 2) = o;
}

// ---------------------------------------------------------------------------
extern "C" void kernel_launch(void* const* d_in, const int* in_sizes, int n_in,
                              void* d_out, int out_size) {
    const float* X     = (const float*)d_in[0];
    const int*   erows = (const int*)  d_in[1];
    const int*   ecols = (const int*)  d_in[2];
    const float* evals = (const float*)d_in[3];
    const float* W     = (const float*)d_in[4];
    const float* bias  = (const float*)d_in[5];
    float*       out   = (float*)d_out;

    dim3 ggrid((N_NODES + 63) / 64, SUPPORT);
    gemm_kernel<<<ggrid, 256>>>(X, W);

    int ebl = (TOT_E + 255) / 256;
    zero_kernel<<<(N_NODES + 255) / 256, 256>>>();
    hist_kernel<<<ebl, 256>>>(erows);
    scanA_kernel<<<NBLK, SCAN_BS>>>();
    scanB_kernel<<<1, 128>>>();
    scanC_kernel<<<NBLK, SCAN_BS>>>();
    scatter_kernel<<<ebl, 256>>>(erows, ecols, evals);

    int ablocks = (N_NODES * 32 + 255) / 256;
    accum_kernel<<<ablocks, 256>>>(bias, out);
}

// round 5
// speedup vs baseline: 1.1028x; 1.0428x over previous
#include <cuda_runtime.h>
#include <cstdint>

#define N_NODES 100000
#define N_EDGES 1600000
#define IN_F 64
#define OUT_F 64
#define SUPPORT 3

#define M_BINS (SUPPORT * N_NODES)                 // 300000 (k,row) bins
#define TOT_E  (SUPPORT * N_EDGES)                 // 4.8M edges
#define SCAN_BS 1024
#define NBLK ((M_BINS + SCAN_BS - 1) / SCAN_BS)    // 293

// ---- static scratch (no runtime allocation) -------------------------------
__device__ float              g_Y[(size_t)SUPPORT * N_NODES * IN_F];  // 76.8 MB: S_k @ X
__device__ int                g_count[M_BINS];
__device__ int                g_start[M_BINS + 1];
__device__ int                g_cursor[M_BINS];
__device__ int                g_partial[SCAN_BS];
__device__ unsigned long long g_pairs[TOT_E];      // (val<<32 | col), bin-sorted

// ---------------------------------------------------------------------------
// Counting sort by (support, destination row)
// ---------------------------------------------------------------------------
__global__ __launch_bounds__(256) void zero_kernel() {
    int i = blockIdx.x * 256 + threadIdx.x;
    if (i < M_BINS) g_count[i] = 0;
}

// 4 edges/thread, vectorized row loads. N_EDGES % 4 == 0 -> one k per group.
__global__ __launch_bounds__(256) void hist_kernel(const int* __restrict__ rows) {
    int g = blockIdx.x * 256 + threadIdx.x;
    if (g >= TOT_E / 4) return;
    int  e0 = g * 4;
    int  k  = e0 / N_EDGES;
    int4 r4 = *reinterpret_cast<const int4*>(rows + e0);
    int  kb = k * N_NODES;
    atomicAdd(&g_count[kb + r4.x], 1);
    atomicAdd(&g_count[kb + r4.y], 1);
    atomicAdd(&g_count[kb + r4.z], 1);
    atomicAdd(&g_count[kb + r4.w], 1);
}

__global__ __launch_bounds__(SCAN_BS) void scanA_kernel() {
    __shared__ int s[SCAN_BS];
    int t = threadIdx.x;
    int i = blockIdx.x * SCAN_BS + t;
    int v = (i < M_BINS) ? g_count[i] : 0;
    s[t] = v;
    __syncthreads();
    #pragma unroll
    for (int off = 1; off < SCAN_BS; off <<= 1) {
        int x = (t >= off) ? s[t - off] : 0;
        __syncthreads();
        s[t] += x;
        __syncthreads();
    }
    if (i < M_BINS) g_start[i] = s[t] - v;
    if (t == SCAN_BS - 1) g_partial[blockIdx.x] = s[t];
}

__global__ __launch_bounds__(512) void scanB_kernel() {
    __shared__ int s[512];
    int t = threadIdx.x;
    int v = (t < NBLK) ? g_partial[t] : 0;
    s[t] = v;
    __syncthreads();
    #pragma unroll
    for (int off = 1; off < 512; off <<= 1) {
        int x = (t >= off) ? s[t - off] : 0;
        __syncthreads();
        s[t] += x;
        __syncthreads();
    }
    if (t < NBLK) g_partial[t] = s[t] - v;
}

__global__ __launch_bounds__(SCAN_BS) void scanC_kernel() {
    int i = blockIdx.x * SCAN_BS + threadIdx.x;
    if (i < M_BINS) {
        int st = g_start[i] + g_partial[blockIdx.x];
        g_start[i]  = st;
        g_cursor[i] = st;
    }
    if (i == 0) g_start[M_BINS] = TOT_E;
}

// 4 edges/thread, vectorized loads, packed 8B payload (val, col).
__global__ __launch_bounds__(256) void scatter_kernel(const int* __restrict__ rows,
                                                      const int* __restrict__ cols,
                                                      const float* __restrict__ vals) {
    int g = blockIdx.x * 256 + threadIdx.x;
    if (g >= TOT_E / 4) return;
    int    e0 = g * 4;
    int    k  = e0 / N_EDGES;
    int4   r4 = *reinterpret_cast<const int4*>(rows + e0);
    int4   c4 = *reinterpret_cast<const int4*>(cols + e0);
    float4 v4 = *reinterpret_cast<const float4*>(vals + e0);
    int    kb = k * N_NODES;

    int p0 = atomicAdd(&g_cursor[kb + r4.x], 1);
    int p1 = atomicAdd(&g_cursor[kb + r4.y], 1);
    int p2 = atomicAdd(&g_cursor[kb + r4.z], 1);
    int p3 = atomicAdd(&g_cursor[kb + r4.w], 1);

    g_pairs[p0] = ((unsigned long long)__float_as_uint(v4.x) << 32) | (unsigned int)c4.x;
    g_pairs[p1] = ((unsigned long long)__float_as_uint(v4.y) << 32) | (unsigned int)c4.y;
    g_pairs[p2] = ((unsigned long long)__float_as_uint(v4.z) << 32) | (unsigned int)c4.z;
    g_pairs[p3] = ((unsigned long long)__float_as_uint(v4.w) << 32) | (unsigned int)c4.w;
}

// ---------------------------------------------------------------------------
// SpMM accumulate: Y[k][n] = sum val * X[col]. One warp per node; gathers hit
// X (25.6 MB, fully L2-resident). 4-way unroll for MLP. No atomics.
// ---------------------------------------------------------------------------
__global__ __launch_bounds__(256) void accum_kernel(const float* __restrict__ X) {
    int t    = blockIdx.x * 256 + threadIdx.x;
    int n    = t >> 5;
    int lane = t & 31;
    if (n >= N_NODES) return;

    #pragma unroll
    for (int k = 0; k < SUPPORT; k++) {
        int bin  = k * N_NODES + n;
        int e    = __ldg(&g_start[bin]);
        int eend = __ldg(&g_start[bin + 1]);

        float2 acc = make_float2(0.f, 0.f);

        for (; e + 4 <= eend; e += 4) {
            unsigned long long p0 = __ldg(g_pairs + e + 0);
            unsigned long long p1 = __ldg(g_pairs + e + 1);
            unsigned long long p2 = __ldg(g_pairs + e + 2);
            unsigned long long p3 = __ldg(g_pairs + e + 3);
            float2 f0 = *reinterpret_cast<const float2*>(X + (size_t)(unsigned int)p0 * IN_F + lane * 2);
            float2 f1 = *reinterpret_cast<const float2*>(X + (size_t)(unsigned int)p1 * IN_F + lane * 2);
            float2 f2 = *reinterpret_cast<const float2*>(X + (size_t)(unsigned int)p2 * IN_F + lane * 2);
            float2 f3 = *reinterpret_cast<const float2*>(X + (size_t)(unsigned int)p3 * IN_F + lane * 2);
            float v0 = __uint_as_float((unsigned int)(p0 >> 32));
            float v1 = __uint_as_float((unsigned int)(p1 >> 32));
            float v2 = __uint_as_float((unsigned int)(p2 >> 32));
            float v3 = __uint_as_float((unsigned int)(p3 >> 32));
            acc.x += v0 * f0.x; acc.y += v0 * f0.y;
            acc.x += v1 * f1.x; acc.y += v1 * f1.y;
            acc.x += v2 * f2.x; acc.y += v2 * f2.y;
            acc.x += v3 * f3.x; acc.y += v3 * f3.y;
        }
        for (; e < eend; e++) {
            unsigned long long p0 = __ldg(g_pairs + e);
            float2 f0 = *reinterpret_cast<const float2*>(X + (size_t)(unsigned int)p0 * IN_F + lane * 2);
            float v0 = __uint_as_float((unsigned int)(p0 >> 32));
            acc.x += v0 * f0.x; acc.y += v0 * f0.y;
        }

        *reinterpret_cast<float2*>(g_Y + ((size_t)k * N_NODES + n) * IN_F + lane * 2) = acc;
    }
}

// ---------------------------------------------------------------------------
// Fused GEMM: out[n][:] = bias + sum_k Y[k][n][:] @ W[k*64:(k+1)*64][:]
// 64x64 tile, 4x4 microtile, all 3 supports accumulated in registers.
// ---------------------------------------------------------------------------
__global__ __launch_bounds__(256) void gemm_kernel(const float* __restrict__ W,
                                                   const float* __restrict__ bias,
                                                   float* __restrict__ out) {
    __shared__ float4 Ys4[64][16];    // [row][j/4]
    __shared__ float4 Ws4[64][16];    // [j][col/4]

    const int rbase = blockIdx.x * 64;
    const int tid   = threadIdx.x;
    const int ty    = tid >> 4;
    const int tx    = tid & 15;

    float acc[4][4];
    #pragma unroll
    for (int i = 0; i < 4; i++)
        #pragma unroll
        for (int c = 0; c < 4; c++) acc[i][c] = 0.f;

    for (int k = 0; k < SUPPORT; k++) {
        const float* Yk = g_Y + (size_t)k * N_NODES * IN_F;
        #pragma unroll
        for (int i = tid; i < 64 * 16; i += 256) {
            int r  = i >> 4;
            int c4 = i & 15;
            int gr = rbase + r;
            float4 v = make_float4(0.f, 0.f, 0.f, 0.f);
            if (gr < N_NODES)
                v = *reinterpret_cast<const float4*>(Yk + (size_t)gr * IN_F + c4 * 4);
            Ys4[r][c4] = v;
        }
        #pragma unroll
        for (int i = tid; i < 64 * 16; i += 256) {
            int j  = i >> 4;
            int c4 = i & 15;
            Ws4[j][c4] = *reinterpret_cast<const float4*>(W + (size_t)(k * 64 + j) * OUT_F + c4 * 4);
        }
        __syncthreads();

        #pragma unroll
        for (int j0 = 0; j0 < 64; j0 += 4) {
            float4 b0 = Ws4[j0 + 0][tx];
            float4 b1 = Ws4[j0 + 1][tx];
            float4 b2 = Ws4[j0 + 2][tx];
            float4 b3 = Ws4[j0 + 3][tx];
            #pragma unroll
            for (int i = 0; i < 4; i++) {
                float4 a = Ys4[ty * 4 + i][j0 >> 2];
                acc[i][0] += a.x * b0.x + a.y * b1.x + a.z * b2.x + a.w * b3.x;
                acc[i][1] += a.x * b0.y + a.y * b1.y + a.z * b2.y + a.w * b3.y;
                acc[i][2] += a.x * b0.z + a.y * b1.z + a.z * b2.z + a.w * b3.z;
                acc[i][3] += a.x * b0.w + a.y * b1.w + a.z * b2.w + a.w * b3.w;
            }
        }
        __syncthreads();
    }

    float4 b4 = *reinterpret_cast<const float4*>(bias + tx * 4);
    #pragma unroll
    for (int i = 0; i < 4; i++) {
        int gr = rbase + ty * 4 + i;
        if (gr < N_NODES) {
            float4 o = make_float4(acc[i][0] + b4.x, acc[i][1] + b4.y,
                                   acc[i][2] + b4.z, acc[i][3] + b4.w);
            *reinterpret_cast<float4*>(out + (size_t)gr * OUT_F + tx * 4) = o;
        }
    }
}

// ---------------------------------------------------------------------------
extern "C" void kernel_launch(void* const* d_in, const int* in_sizes, int n_in,
                              void* d_out, int out_size) {
    const float* X     = (const float*)d_in[0];
    const int*   erows = (const int*)  d_in[1];
    const int*   ecols = (const int*)  d_in[2];
    const float* evals = (const float*)d_in[3];
    const float* W     = (const float*)d_in[4];
    const float* bias  = (const float*)d_in[5];
    float*       out   = (float*)d_out;

    int ebl4 = (TOT_E / 4 + 255) / 256;
    zero_kernel<<<(M_BINS + 255) / 256, 256>>>();
    hist_kernel<<<ebl4, 256>>>(erows);
    scanA_kernel<<<NBLK, SCAN_BS>>>();
    scanB_kernel<<<1, 512>>>();
    scanC_kernel<<<NBLK, SCAN_BS>>>();
    scatter_kernel<<<ebl4, 256>>>(erows, ecols, evals);

    // Y[k] = S_k @ X  (gathers from L2-resident X)
    int ablocks = (N_NODES * 32 + 255) / 256;
    accum_kernel<<<ablocks, 256>>>(X);

    // out = concat_k(Y_k) @ W + bias
    gemm_kernel<<<(N_NODES + 63) / 64, 256>>>(W, bias, out);
}